// round 3
// baseline (speedup 1.0000x reference)
#include <cuda_runtime.h>
#include <cuda_bf16.h>

// AttentionLayer: out[b,u] = sum_t softmax_t(tanh(x[b,t,:]·W + b[t])) * x[b,t,u]
// B=256, T=2048, U=512, fp32.
//
// Single fused pass: since tanh(...) in (-1,1), exp() needs no max-subtraction,
// so softmax = (sum exp(e_t) x_t) / (sum exp(e_t)) computed online.
// x (1 GiB) is read from HBM exactly once -> HBM-bound streaming kernel.

#define T_DIM 2048
#define U_DIM 512
#define NWARP 16
#define TPW   (T_DIM / NWARP)   // 128 timesteps per warp

__global__ __launch_bounds__(512, 2)
void attn_pool_kernel(const float* __restrict__ x,
                      const float* __restrict__ W,
                      const float* __restrict__ bvec,
                      float* __restrict__ out)
{
    __shared__ float sacc[NWARP * U_DIM];   // 32 KB: per-warp partial accumulators
    __shared__ float ssum[NWARP];           // per-warp partial softmax denominators

    const int batch = blockIdx.x;
    const int tid   = threadIdx.x;
    const int warp  = tid >> 5;
    const int lane  = tid & 31;

    // Per-lane W slice: lane holds u = c*128 + lane*4 + {0..3}, c = 0..3
    float4 wv[4];
#pragma unroll
    for (int c = 0; c < 4; c++)
        wv[c] = reinterpret_cast<const float4*>(W)[c * 32 + lane];

    float4 acc[4];
#pragma unroll
    for (int c = 0; c < 4; c++)
        acc[c] = make_float4(0.f, 0.f, 0.f, 0.f);
    float s = 0.f;

    const float4* xb = reinterpret_cast<const float4*>(
        x + (size_t)batch * T_DIM * U_DIM);

    const int t0 = warp * TPW;   // contiguous timestep slab per warp

    for (int i = 0; i < TPW; i++) {
        const int t = t0 + i;

        // Load full 512-float row across the warp: 4x float4 per lane, coalesced.
        float4 xv[4];
#pragma unroll
        for (int c = 0; c < 4; c++)
            xv[c] = xb[(size_t)t * 128 + c * 32 + lane];

        // Partial dot with W
        float p = 0.f;
#pragma unroll
        for (int c = 0; c < 4; c++)
            p += xv[c].x * wv[c].x + xv[c].y * wv[c].y
               + xv[c].z * wv[c].z + xv[c].w * wv[c].w;

        // Warp-wide reduction (butterfly -> every lane has full dot)
#pragma unroll
        for (int o = 16; o > 0; o >>= 1)
            p += __shfl_xor_sync(0xffffffffu, p, o);

        const float e = tanhf(p + bvec[t]);
        const float w = __expf(e);           // safe: e in (-1,1)
        s += w;

        // Accumulate weighted row while xv is still in registers
#pragma unroll
        for (int c = 0; c < 4; c++) {
            acc[c].x += w * xv[c].x;
            acc[c].y += w * xv[c].y;
            acc[c].z += w * xv[c].z;
            acc[c].w += w * xv[c].w;
        }
    }

    // Stash per-warp partials in shared memory
#pragma unroll
    for (int c = 0; c < 4; c++)
        reinterpret_cast<float4*>(sacc + warp * U_DIM)[c * 32 + lane] = acc[c];
    if (lane == 0) ssum[warp] = s;
    __syncthreads();

    // Cross-warp reduction: thread `tid` owns output element u = tid (0..511)
    float stot = 0.f;
#pragma unroll
    for (int w_ = 0; w_ < NWARP; w_++) stot += ssum[w_];
    const float inv = 1.0f / stot;

    float v = 0.f;
#pragma unroll
    for (int w_ = 0; w_ < NWARP; w_++)
        v += sacc[w_ * U_DIM + tid];        // conflict-free: consecutive tids

    out[(size_t)batch * U_DIM + tid] = v * inv;
}

extern "C" void kernel_launch(void* const* d_in, const int* in_sizes, int n_in,
                              void* d_out, int out_size)
{
    const float* x  = (const float*)d_in[0];   // (256, 2048, 512) f32
    const float* W  = (const float*)d_in[1];   // (512, 1) f32
    const float* bv = (const float*)d_in[2];   // (2048, 1) f32
    float* out = (float*)d_out;                // (256, 512) f32

    attn_pool_kernel<<<256, 512>>>(x, W, bv, out);
}